// round 1
// baseline (speedup 1.0000x reference)
#include <cuda_runtime.h>
#include <cuda_bf16.h>
#include <math.h>

#define LSEQ   2048
#define DMODEL 512
#define NLAYER 8
#define DSTATE 16
#define DCONV  4
#define DINNER 1024
#define DTRANK 32
#define VOCAB  4096
#define XDIM   64   // DTRANK + 2*DSTATE

// ---------------- scratch (static device globals; no allocation) ----------------
__device__ float g_h[LSEQ * DMODEL];
__device__ float g_x[LSEQ * DMODEL];
__device__ float g_xz[LSEQ * 2 * DINNER];
__device__ float g_u[LSEQ * DINNER];
__device__ float g_xdbl[LSEQ * XDIM];
__device__ float g_delta[LSEQ * DINNER];
__device__ float g_y[LSEQ * DINNER];
__device__ float g_yf[LSEQ * DINNER];
__device__ float g_loss[2];

// ---------------- block reductions ----------------
__device__ __forceinline__ float blockReduceSum(float v) {
    __shared__ float sh[9];
    int lane = threadIdx.x & 31, w = threadIdx.x >> 5;
    #pragma unroll
    for (int o = 16; o; o >>= 1) v += __shfl_xor_sync(0xffffffffu, v, o);
    if (lane == 0) sh[w] = v;
    __syncthreads();
    if (threadIdx.x == 0) {
        float s = 0.f;
        int nw = (blockDim.x + 31) >> 5;
        for (int i = 0; i < nw; i++) s += sh[i];
        sh[8] = s;
    }
    __syncthreads();
    float r = sh[8];
    __syncthreads();
    return r;
}

__device__ __forceinline__ float blockReduceMax(float v) {
    __shared__ float sh[9];
    int lane = threadIdx.x & 31, w = threadIdx.x >> 5;
    #pragma unroll
    for (int o = 16; o; o >>= 1) v = fmaxf(v, __shfl_xor_sync(0xffffffffu, v, o));
    if (lane == 0) sh[w] = v;
    __syncthreads();
    if (threadIdx.x == 0) {
        float s = -1e30f;
        int nw = (blockDim.x + 31) >> 5;
        for (int i = 0; i < nw; i++) s = fmaxf(s, sh[i]);
        sh[8] = s;
    }
    __syncthreads();
    float r = sh[8];
    __syncthreads();
    return r;
}

// ---------------- embedding ----------------
__global__ void embed_kernel(const int* __restrict__ ids,
                             const float* __restrict__ emb,
                             const float* __restrict__ pos) {
    int i = blockIdx.x * blockDim.x + threadIdx.x;
    if (i >= LSEQ * DMODEL) return;
    int t = i / DMODEL;
    int d = i - t * DMODEL;
    g_h[i] = emb[(size_t)ids[t] * DMODEL + d] + pos[i];
}

// ---------------- rmsnorm: one block per token, 256 threads ----------------
__global__ void rmsnorm_kernel(const float* __restrict__ src,
                               const float* __restrict__ w,
                               float* __restrict__ dst) {
    int t = blockIdx.x;
    const float* r = src + (size_t)t * DMODEL;
    float v0 = r[threadIdx.x];
    float v1 = r[threadIdx.x + 256];
    float ss = blockReduceSum(v0 * v0 + v1 * v1);
    float sc = rsqrtf(ss * (1.0f / DMODEL) + 1e-6f);
    dst[(size_t)t * DMODEL + threadIdx.x]        = v0 * sc * w[threadIdx.x];
    dst[(size_t)t * DMODEL + threadIdx.x + 256]  = v1 * sc * w[threadIdx.x + 256];
}

// ---------------- SGEMM: C[M,N] = A[M,K] * B[N,K]^T  (+epilogue) ----------------
// EPI: 0 = plain store, 1 = softplus(v + bias[col]), 2 = v + resid[row,col]
template <int EPI>
__global__ void sgemm_kernel(int M, int N, int K,
                             const float* __restrict__ A, int lda,
                             const float* __restrict__ B, int ldb,
                             float* __restrict__ C, int ldc,
                             const float* __restrict__ bias,
                             const float* __restrict__ resid) {
    const int BM = 64, BN = 64, BK = 16;
    __shared__ float As[BK][BM + 4];
    __shared__ float Bs[BK][BN + 4];
    int tid = threadIdx.x;
    int bm0 = blockIdx.y * BM, bn0 = blockIdx.x * BN;
    int ty = tid >> 4, tx = tid & 15;
    int lrow = tid >> 2;           // 0..63
    int lc4  = (tid & 3) << 2;     // 0,4,8,12

    float acc[4][4];
    #pragma unroll
    for (int i = 0; i < 4; i++)
        #pragma unroll
        for (int j = 0; j < 4; j++) acc[i][j] = 0.f;

    for (int k0 = 0; k0 < K; k0 += BK) {
        float4 av = *reinterpret_cast<const float4*>(&A[(size_t)(bm0 + lrow) * lda + k0 + lc4]);
        float4 bv = *reinterpret_cast<const float4*>(&B[(size_t)(bn0 + lrow) * ldb + k0 + lc4]);
        __syncthreads();
        As[lc4 + 0][lrow] = av.x; As[lc4 + 1][lrow] = av.y;
        As[lc4 + 2][lrow] = av.z; As[lc4 + 3][lrow] = av.w;
        Bs[lc4 + 0][lrow] = bv.x; Bs[lc4 + 1][lrow] = bv.y;
        Bs[lc4 + 2][lrow] = bv.z; Bs[lc4 + 3][lrow] = bv.w;
        __syncthreads();
        #pragma unroll
        for (int kk = 0; kk < BK; kk++) {
            float4 a4 = *reinterpret_cast<const float4*>(&As[kk][ty * 4]);
            float4 b4 = *reinterpret_cast<const float4*>(&Bs[kk][tx * 4]);
            float a[4] = {a4.x, a4.y, a4.z, a4.w};
            float b[4] = {b4.x, b4.y, b4.z, b4.w};
            #pragma unroll
            for (int i = 0; i < 4; i++)
                #pragma unroll
                for (int j = 0; j < 4; j++)
                    acc[i][j] = fmaf(a[i], b[j], acc[i][j]);
        }
    }

    #pragma unroll
    for (int i = 0; i < 4; i++) {
        int row = bm0 + ty * 4 + i;
        #pragma unroll
        for (int j = 0; j < 4; j++) {
            int col = bn0 + tx * 4 + j;
            float v = acc[i][j];
            if (EPI == 1) {
                v += bias[col];
                v = (v > 20.f) ? v : log1pf(expf(v));   // softplus
            }
            if (EPI == 2) {
                v += resid[(size_t)row * ldc + col];
            }
            C[(size_t)row * ldc + col] = v;
        }
    }
}

// ---------------- depthwise causal conv (width 4) + bias + silu ----------------
__global__ void conv_silu_kernel(const float* __restrict__ cw,
                                 const float* __restrict__ cb) {
    int i = blockIdx.x * blockDim.x + threadIdx.x;
    if (i >= LSEQ * DINNER) return;
    int c = i & (DINNER - 1);
    int t = i >> 10;
    float v = cb[c];
    #pragma unroll
    for (int k = 0; k < DCONV; k++) {
        int tt = t - (DCONV - 1) + k;
        if (tt >= 0)
            v = fmaf(g_xz[(size_t)tt * (2 * DINNER) + c], cw[c * DCONV + k], v);
    }
    g_u[i] = v / (1.f + expf(-v));   // silu
}

// ---------------- selective scan ----------------
// lane layout: 2 channels per warp, 16 state-lanes per channel.
// h_{t} = exp(delta*A) * h_{t-1} + delta*u*B[t,s];  y[t,d] = sum_s h*C[t,s]
__global__ void scan_kernel(const float* __restrict__ delta,
                            const float* __restrict__ u,
                            const float* __restrict__ xdbl,
                            const float* __restrict__ A_log,
                            float* __restrict__ y) {
    int warp = threadIdx.x >> 5;
    int lane = threadIdx.x & 31;
    int half = lane >> 4;
    int s    = lane & 15;
    int ch   = blockIdx.x * 8 + warp * 2 + half;

    float A2 = -__expf(A_log[ch * DSTATE + s]) * 1.44269504088896f;  // A * log2(e)
    float h = 0.f;
    const float* Bp = xdbl + DTRANK;            // B at cols [32,48)
    const float* Cp = xdbl + DTRANK + DSTATE;   // C at cols [48,64)

    for (int t0 = 0; t0 < LSEQ; t0 += 16) {
        float dv[16], uv[16], bv[16], cv[16];
        #pragma unroll
        for (int j = 0; j < 16; j++) {
            int t = t0 + j;
            dv[j] = delta[(size_t)t * DINNER + ch];
            uv[j] = u[(size_t)t * DINNER + ch];
            bv[j] = Bp[(size_t)t * XDIM + s];
            cv[j] = Cp[(size_t)t * XDIM + s];
        }
        float p[16];
        #pragma unroll
        for (int j = 0; j < 16; j++) {
            float dA  = exp2f(dv[j] * A2);
            float dbu = dv[j] * uv[j] * bv[j];
            h = fmaf(dA, h, dbu);
            p[j] = h * cv[j];
        }
        float out = 0.f;
        #pragma unroll
        for (int j = 0; j < 16; j++) {
            float v = p[j];
            v += __shfl_xor_sync(0xffffffffu, v, 1);
            v += __shfl_xor_sync(0xffffffffu, v, 2);
            v += __shfl_xor_sync(0xffffffffu, v, 4);
            v += __shfl_xor_sync(0xffffffffu, v, 8);
            if (s == j) out = v;
        }
        y[(size_t)(t0 + s) * DINNER + ch] = out;
    }
}

// ---------------- y = (scan_y + u*Dp) * silu(z) ----------------
__global__ void ycomb_kernel(const float* __restrict__ Dp) {
    int i = blockIdx.x * blockDim.x + threadIdx.x;
    if (i >= LSEQ * DINNER) return;
    int c = i & (DINNER - 1);
    int t = i >> 10;
    float z = g_xz[(size_t)t * (2 * DINNER) + DINNER + c];
    float sz = z / (1.f + expf(-z));
    g_yf[i] = (g_y[i] + g_u[i] * Dp[c]) * sz;
}

// ---------------- cross-entropy loss over logits ----------------
__global__ void loss_init_kernel() { g_loss[0] = 0.f; g_loss[1] = 0.f; }

__global__ void loss_kernel(const int* __restrict__ labels,
                            const float* __restrict__ logits) {
    int t = blockIdx.x;   // 0..L-2
    const float* row = logits + (size_t)t * VOCAB;
    float mx = -1e30f;
    for (int j = threadIdx.x; j < VOCAB; j += 256) mx = fmaxf(mx, row[j]);
    mx = blockReduceMax(mx);
    float sum = 0.f;
    for (int j = threadIdx.x; j < VOCAB; j += 256) sum += expf(row[j] - mx);
    sum = blockReduceSum(sum);
    if (threadIdx.x == 0) {
        int tgt = labels[t + 1];
        if (tgt != -100) {
            float lp = row[tgt] - mx - logf(sum);
            atomicAdd(&g_loss[0], -lp);
            atomicAdd(&g_loss[1], 1.f);
        }
    }
}

__global__ void loss_final_kernel(float* __restrict__ out, int idx) {
    out[idx] = g_loss[0] / fmaxf(g_loss[1], 1.f);
}

// ---------------- driver ----------------
extern "C" void kernel_launch(void* const* d_in, const int* in_sizes, int n_in,
                              void* d_out, int out_size) {
    const int*   ids    = (const int*)  d_in[0];
    const int*   labels = (const int*)  d_in[1];
    const float* emb    = (const float*)d_in[2];
    const float* pos    = (const float*)d_in[3];
    const float* fnw    = (const float*)d_in[4];
    const float* nw     = (const float*)d_in[5];
    const float* inw    = (const float*)d_in[6];
    const float* cw     = (const float*)d_in[7];
    const float* cb     = (const float*)d_in[8];
    const float* xw     = (const float*)d_in[9];
    const float* dw     = (const float*)d_in[10];
    const float* db     = (const float*)d_in[11];
    const float* alog   = (const float*)d_in[12];
    const float* dp     = (const float*)d_in[13];
    const float* ow     = (const float*)d_in[14];
    float* out = (float*)d_out;

    float *ph, *px, *pxz, *pu, *pxd, *pdelta, *py, *pyf;
    cudaGetSymbolAddress((void**)&ph,     g_h);
    cudaGetSymbolAddress((void**)&px,     g_x);
    cudaGetSymbolAddress((void**)&pxz,    g_xz);
    cudaGetSymbolAddress((void**)&pu,     g_u);
    cudaGetSymbolAddress((void**)&pxd,    g_xdbl);
    cudaGetSymbolAddress((void**)&pdelta, g_delta);
    cudaGetSymbolAddress((void**)&py,     g_y);
    cudaGetSymbolAddress((void**)&pyf,    g_yf);

    embed_kernel<<<(LSEQ * DMODEL + 255) / 256, 256>>>(ids, emb, pos);

    for (int l = 0; l < NLAYER; l++) {
        const float* nw_l  = nw   + (size_t)l * DMODEL;
        const float* inw_l = inw  + (size_t)l * 2 * DINNER * DMODEL;
        const float* cw_l  = cw   + (size_t)l * DINNER * DCONV;
        const float* cb_l  = cb   + (size_t)l * DINNER;
        const float* xw_l  = xw   + (size_t)l * XDIM * DINNER;
        const float* dw_l  = dw   + (size_t)l * DINNER * DTRANK;
        const float* db_l  = db   + (size_t)l * DINNER;
        const float* al_l  = alog + (size_t)l * DINNER * DSTATE;
        const float* dp_l  = dp   + (size_t)l * DINNER;
        const float* ow_l  = ow   + (size_t)l * DMODEL * DINNER;

        // x = rmsnorm(h)
        rmsnorm_kernel<<<LSEQ, 256>>>(ph, nw_l, px);
        // xz = x @ in_w^T   [2048 x 2048]
        sgemm_kernel<0><<<dim3(2 * DINNER / 64, LSEQ / 64), 256>>>(
            LSEQ, 2 * DINNER, DMODEL, px, DMODEL, inw_l, DMODEL, pxz, 2 * DINNER,
            nullptr, nullptr);
        // u = silu(causal depthwise conv(xi) + b)
        conv_silu_kernel<<<(LSEQ * DINNER + 255) / 256, 256>>>(cw_l, cb_l);
        // xdbl = u @ xproj_w^T   [2048 x 64]
        sgemm_kernel<0><<<dim3(XDIM / 64, LSEQ / 64), 256>>>(
            LSEQ, XDIM, DINNER, pu, DINNER, xw_l, DINNER, pxd, XDIM,
            nullptr, nullptr);
        // delta = softplus(dt @ dt_w^T + dt_b)   [2048 x 1024]
        sgemm_kernel<1><<<dim3(DINNER / 64, LSEQ / 64), 256>>>(
            LSEQ, DINNER, DTRANK, pxd, XDIM, dw_l, DTRANK, pdelta, DINNER,
            db_l, nullptr);
        // selective scan -> y
        scan_kernel<<<DINNER / 8, 128>>>(pdelta, pu, pxd, al_l, py);
        // yf = (y + u*Dp) * silu(z)
        ycomb_kernel<<<(LSEQ * DINNER + 255) / 256, 256>>>(dp_l);
        // h = h + yf @ out_w^T   [2048 x 512]
        sgemm_kernel<2><<<dim3(DMODEL / 64, LSEQ / 64), 256>>>(
            LSEQ, DMODEL, DINNER, pyf, DINNER, ow_l, DINNER, ph, DMODEL,
            nullptr, ph);
    }

    // final norm + logits
    rmsnorm_kernel<<<LSEQ, 256>>>(ph, fnw, px);
    sgemm_kernel<0><<<dim3(VOCAB / 64, LSEQ / 64), 256>>>(
        LSEQ, VOCAB, DMODEL, px, DMODEL, emb, DMODEL, out, VOCAB,
        nullptr, nullptr);

    // loss
    loss_init_kernel<<<1, 1>>>();
    loss_kernel<<<LSEQ - 1, 256>>>(labels, out);
    loss_final_kernel<<<1, 1>>>(out, out_size - 1);
}

// round 2
// speedup vs baseline: 1.5766x; 1.5766x over previous
#include <cuda_runtime.h>
#include <cuda_bf16.h>
#include <math.h>

#define LSEQ   2048
#define DMODEL 512
#define NLAYER 8
#define DSTATE 16
#define DCONV  4
#define DINNER 1024
#define DTRANK 32
#define VOCAB  4096
#define XDIM   64   // DTRANK + 2*DSTATE

// ---------------- scratch (static device globals; no allocation) ----------------
__device__ float g_h[LSEQ * DMODEL];
__device__ float g_x[LSEQ * DMODEL];
__device__ float g_xz[LSEQ * 2 * DINNER];
__device__ float g_u[LSEQ * DINNER];
__device__ float g_xdbl[LSEQ * XDIM];
__device__ float g_xpart[4 * LSEQ * XDIM];
__device__ float g_delta[LSEQ * DINNER];
__device__ float g_yf[LSEQ * DINNER];
__device__ float g_loss[2];

// ---------------- block reductions ----------------
__device__ __forceinline__ float blockReduceSum(float v) {
    __shared__ float sh[9];
    int lane = threadIdx.x & 31, w = threadIdx.x >> 5;
    #pragma unroll
    for (int o = 16; o; o >>= 1) v += __shfl_xor_sync(0xffffffffu, v, o);
    if (lane == 0) sh[w] = v;
    __syncthreads();
    if (threadIdx.x == 0) {
        float s = 0.f;
        int nw = (blockDim.x + 31) >> 5;
        for (int i = 0; i < nw; i++) s += sh[i];
        sh[8] = s;
    }
    __syncthreads();
    float r = sh[8];
    __syncthreads();
    return r;
}

__device__ __forceinline__ float blockReduceMax(float v) {
    __shared__ float sh[9];
    int lane = threadIdx.x & 31, w = threadIdx.x >> 5;
    #pragma unroll
    for (int o = 16; o; o >>= 1) v = fmaxf(v, __shfl_xor_sync(0xffffffffu, v, o));
    if (lane == 0) sh[w] = v;
    __syncthreads();
    if (threadIdx.x == 0) {
        float s = -1e30f;
        int nw = (blockDim.x + 31) >> 5;
        for (int i = 0; i < nw; i++) s = fmaxf(s, sh[i]);
        sh[8] = s;
    }
    __syncthreads();
    float r = sh[8];
    __syncthreads();
    return r;
}

// ---------------- embedding ----------------
__global__ void embed_kernel(const int* __restrict__ ids,
                             const float* __restrict__ emb,
                             const float* __restrict__ pos) {
    int i = blockIdx.x * blockDim.x + threadIdx.x;
    if (i >= LSEQ * DMODEL) return;
    int t = i / DMODEL;
    int d = i - t * DMODEL;
    g_h[i] = emb[(size_t)ids[t] * DMODEL + d] + pos[i];
}

// ---------------- rmsnorm: one block per token, 256 threads ----------------
__global__ void rmsnorm_kernel(const float* __restrict__ src,
                               const float* __restrict__ w,
                               float* __restrict__ dst) {
    int t = blockIdx.x;
    const float* r = src + (size_t)t * DMODEL;
    float v0 = r[threadIdx.x];
    float v1 = r[threadIdx.x + 256];
    float ss = blockReduceSum(v0 * v0 + v1 * v1);
    float sc = rsqrtf(ss * (1.0f / DMODEL) + 1e-6f);
    dst[(size_t)t * DMODEL + threadIdx.x]        = v0 * sc * w[threadIdx.x];
    dst[(size_t)t * DMODEL + threadIdx.x + 256]  = v1 * sc * w[threadIdx.x + 256];
}

// =================================================================================
// GEMM 128x128x16, double-buffered, 256 threads, 8x8 per thread.
// C[M,N] = A[M,K] * B[N,K]^T.  EPI: 0 = store, 2 = += resid
// =================================================================================
template <int EPI>
__global__ void __launch_bounds__(256) gemm128_kernel(
    int K,
    const float* __restrict__ A, int lda,
    const float* __restrict__ B, int ldb,
    float* __restrict__ C, int ldc,
    const float* __restrict__ resid) {
    __shared__ float As[2][16][132];
    __shared__ float Bs[2][16][132];
    const int tid = threadIdx.x;
    const int bm0 = blockIdx.y * 128, bn0 = blockIdx.x * 128;

    const int ar0 = tid >> 2;            // 0..63
    const int kq0 = (tid & 3) << 2;      // 0,4,8,12

    const float* Ap0 = A + (size_t)(bm0 + ar0) * lda + kq0;
    const float* Ap1 = A + (size_t)(bm0 + 64 + ar0) * lda + kq0;
    const float* Bp0 = B + (size_t)(bn0 + ar0) * ldb + kq0;
    const float* Bp1 = B + (size_t)(bn0 + 64 + ar0) * ldb + kq0;

    const int wid = tid >> 5, lane = tid & 31;
    const int r0 = (wid >> 2) * 64 + (lane >> 2) * 8;  // row base in tile
    const int c0 = (wid & 3) * 32 + (lane & 3) * 8;    // col base in tile

    float acc[8][8];
    #pragma unroll
    for (int i = 0; i < 8; i++)
        #pragma unroll
        for (int j = 0; j < 8; j++) acc[i][j] = 0.f;

    float4 a0v = *reinterpret_cast<const float4*>(Ap0);
    float4 a1v = *reinterpret_cast<const float4*>(Ap1);
    float4 b0v = *reinterpret_cast<const float4*>(Bp0);
    float4 b1v = *reinterpret_cast<const float4*>(Bp1);
    As[0][kq0 + 0][ar0] = a0v.x; As[0][kq0 + 1][ar0] = a0v.y;
    As[0][kq0 + 2][ar0] = a0v.z; As[0][kq0 + 3][ar0] = a0v.w;
    As[0][kq0 + 0][64 + ar0] = a1v.x; As[0][kq0 + 1][64 + ar0] = a1v.y;
    As[0][kq0 + 2][64 + ar0] = a1v.z; As[0][kq0 + 3][64 + ar0] = a1v.w;
    Bs[0][kq0 + 0][ar0] = b0v.x; Bs[0][kq0 + 1][ar0] = b0v.y;
    Bs[0][kq0 + 2][ar0] = b0v.z; Bs[0][kq0 + 3][ar0] = b0v.w;
    Bs[0][kq0 + 0][64 + ar0] = b1v.x; Bs[0][kq0 + 1][64 + ar0] = b1v.y;
    Bs[0][kq0 + 2][64 + ar0] = b1v.z; Bs[0][kq0 + 3][64 + ar0] = b1v.w;
    __syncthreads();

    const int KT = K >> 4;
    for (int kt = 0; kt < KT; kt++) {
        const int cur = kt & 1, nxt = cur ^ 1;
        if (kt + 1 < KT) {
            int off = (kt + 1) << 4;
            a0v = *reinterpret_cast<const float4*>(Ap0 + off);
            a1v = *reinterpret_cast<const float4*>(Ap1 + off);
            b0v = *reinterpret_cast<const float4*>(Bp0 + off);
            b1v = *reinterpret_cast<const float4*>(Bp1 + off);
        }
        #pragma unroll
        for (int kk = 0; kk < 16; kk++) {
            float4 af0 = *reinterpret_cast<const float4*>(&As[cur][kk][r0]);
            float4 af1 = *reinterpret_cast<const float4*>(&As[cur][kk][r0 + 4]);
            float4 bf0 = *reinterpret_cast<const float4*>(&Bs[cur][kk][c0]);
            float4 bf1 = *reinterpret_cast<const float4*>(&Bs[cur][kk][c0 + 4]);
            float a[8] = {af0.x, af0.y, af0.z, af0.w, af1.x, af1.y, af1.z, af1.w};
            float b[8] = {bf0.x, bf0.y, bf0.z, bf0.w, bf1.x, bf1.y, bf1.z, bf1.w};
            #pragma unroll
            for (int i = 0; i < 8; i++)
                #pragma unroll
                for (int j = 0; j < 8; j++)
                    acc[i][j] = fmaf(a[i], b[j], acc[i][j]);
        }
        if (kt + 1 < KT) {
            As[nxt][kq0 + 0][ar0] = a0v.x; As[nxt][kq0 + 1][ar0] = a0v.y;
            As[nxt][kq0 + 2][ar0] = a0v.z; As[nxt][kq0 + 3][ar0] = a0v.w;
            As[nxt][kq0 + 0][64 + ar0] = a1v.x; As[nxt][kq0 + 1][64 + ar0] = a1v.y;
            As[nxt][kq0 + 2][64 + ar0] = a1v.z; As[nxt][kq0 + 3][64 + ar0] = a1v.w;
            Bs[nxt][kq0 + 0][ar0] = b0v.x; Bs[nxt][kq0 + 1][ar0] = b0v.y;
            Bs[nxt][kq0 + 2][ar0] = b0v.z; Bs[nxt][kq0 + 3][ar0] = b0v.w;
            Bs[nxt][kq0 + 0][64 + ar0] = b1v.x; Bs[nxt][kq0 + 1][64 + ar0] = b1v.y;
            Bs[nxt][kq0 + 2][64 + ar0] = b1v.z; Bs[nxt][kq0 + 3][64 + ar0] = b1v.w;
            __syncthreads();
        }
    }

    #pragma unroll
    for (int i = 0; i < 8; i++) {
        int row = bm0 + r0 + i;
        float* cp = C + (size_t)row * ldc + bn0 + c0;
        float4 v0 = make_float4(acc[i][0], acc[i][1], acc[i][2], acc[i][3]);
        float4 v1 = make_float4(acc[i][4], acc[i][5], acc[i][6], acc[i][7]);
        if (EPI == 2) {
            const float* rp = resid + (size_t)row * ldc + bn0 + c0;
            float4 r4 = *reinterpret_cast<const float4*>(rp);
            float4 r5 = *reinterpret_cast<const float4*>(rp + 4);
            v0.x += r4.x; v0.y += r4.y; v0.z += r4.z; v0.w += r4.w;
            v1.x += r5.x; v1.y += r5.y; v1.z += r5.z; v1.w += r5.w;
        }
        *reinterpret_cast<float4*>(cp)     = v0;
        *reinterpret_cast<float4*>(cp + 4) = v1;
    }
}

// =================================================================================
// GEMM 64x64x16, double-buffered, 256 threads, 4x4 per thread.
// Supports split-K via blockIdx.z: processes k in [z*Kloc, (z+1)*Kloc),
// writing to C + z*partStride.
// EPI: 0 = store, 1 = softplus(v + bias[col]), 2 = += resid
// =================================================================================
template <int EPI>
__global__ void __launch_bounds__(256) gemm64_kernel(
    int Kloc,
    const float* __restrict__ A, int lda,
    const float* __restrict__ B, int ldb,
    float* __restrict__ C, int ldc, int partStride,
    const float* __restrict__ bias,
    const float* __restrict__ resid) {
    __shared__ float As[2][16][68];
    __shared__ float Bs[2][16][68];
    const int tid = threadIdx.x;
    const int bm0 = blockIdx.y * 64, bn0 = blockIdx.x * 64;
    const int kbase = blockIdx.z * Kloc;
    C += (size_t)blockIdx.z * partStride;

    const int lrow = tid >> 2;           // 0..63
    const int kq0  = (tid & 3) << 2;     // 0,4,8,12
    const float* Ap = A + (size_t)(bm0 + lrow) * lda + kbase + kq0;
    const float* Bp = B + (size_t)(bn0 + lrow) * ldb + kbase + kq0;

    const int ty = tid >> 4, tx = tid & 15;

    float acc[4][4];
    #pragma unroll
    for (int i = 0; i < 4; i++)
        #pragma unroll
        for (int j = 0; j < 4; j++) acc[i][j] = 0.f;

    float4 av = *reinterpret_cast<const float4*>(Ap);
    float4 bv = *reinterpret_cast<const float4*>(Bp);
    As[0][kq0 + 0][lrow] = av.x; As[0][kq0 + 1][lrow] = av.y;
    As[0][kq0 + 2][lrow] = av.z; As[0][kq0 + 3][lrow] = av.w;
    Bs[0][kq0 + 0][lrow] = bv.x; Bs[0][kq0 + 1][lrow] = bv.y;
    Bs[0][kq0 + 2][lrow] = bv.z; Bs[0][kq0 + 3][lrow] = bv.w;
    __syncthreads();

    const int KT = Kloc >> 4;
    for (int kt = 0; kt < KT; kt++) {
        const int cur = kt & 1, nxt = cur ^ 1;
        if (kt + 1 < KT) {
            int off = (kt + 1) << 4;
            av = *reinterpret_cast<const float4*>(Ap + off);
            bv = *reinterpret_cast<const float4*>(Bp + off);
        }
        #pragma unroll
        for (int kk = 0; kk < 16; kk++) {
            float4 a4 = *reinterpret_cast<const float4*>(&As[cur][kk][ty * 4]);
            float4 b4 = *reinterpret_cast<const float4*>(&Bs[cur][kk][tx * 4]);
            float a[4] = {a4.x, a4.y, a4.z, a4.w};
            float b[4] = {b4.x, b4.y, b4.z, b4.w};
            #pragma unroll
            for (int i = 0; i < 4; i++)
                #pragma unroll
                for (int j = 0; j < 4; j++)
                    acc[i][j] = fmaf(a[i], b[j], acc[i][j]);
        }
        if (kt + 1 < KT) {
            As[nxt][kq0 + 0][lrow] = av.x; As[nxt][kq0 + 1][lrow] = av.y;
            As[nxt][kq0 + 2][lrow] = av.z; As[nxt][kq0 + 3][lrow] = av.w;
            Bs[nxt][kq0 + 0][lrow] = bv.x; Bs[nxt][kq0 + 1][lrow] = bv.y;
            Bs[nxt][kq0 + 2][lrow] = bv.z; Bs[nxt][kq0 + 3][lrow] = bv.w;
            __syncthreads();
        }
    }

    float4 bias4;
    if (EPI == 1) bias4 = *reinterpret_cast<const float4*>(&bias[bn0 + tx * 4]);

    #pragma unroll
    for (int i = 0; i < 4; i++) {
        int row = bm0 + ty * 4 + i;
        float* cp = C + (size_t)row * ldc + bn0 + tx * 4;
        float4 v = make_float4(acc[i][0], acc[i][1], acc[i][2], acc[i][3]);
        if (EPI == 1) {
            v.x += bias4.x; v.y += bias4.y; v.z += bias4.z; v.w += bias4.w;
            v.x = (v.x > 20.f) ? v.x : log1pf(expf(v.x));
            v.y = (v.y > 20.f) ? v.y : log1pf(expf(v.y));
            v.z = (v.z > 20.f) ? v.z : log1pf(expf(v.z));
            v.w = (v.w > 20.f) ? v.w : log1pf(expf(v.w));
        }
        if (EPI == 2) {
            float4 r4 = *reinterpret_cast<const float4*>(
                resid + (size_t)row * ldc + bn0 + tx * 4);
            v.x += r4.x; v.y += r4.y; v.z += r4.z; v.w += r4.w;
        }
        *reinterpret_cast<float4*>(cp) = v;
    }
}

// ---------------- reduce the 4 split-K partials of xproj ----------------
__global__ void reduce4_kernel(float* __restrict__ dst) {
    int i = blockIdx.x * blockDim.x + threadIdx.x;
    if (i >= LSEQ * XDIM) return;
    dst[i] = g_xpart[i] + g_xpart[i + LSEQ * XDIM]
           + g_xpart[i + 2 * LSEQ * XDIM] + g_xpart[i + 3 * LSEQ * XDIM];
}

// ---------------- depthwise causal conv (width 4) + bias + silu ----------------
__global__ void conv_silu_kernel(const float* __restrict__ cw,
                                 const float* __restrict__ cb) {
    int i = blockIdx.x * blockDim.x + threadIdx.x;
    if (i >= LSEQ * DINNER) return;
    int c = i & (DINNER - 1);
    int t = i >> 10;
    float v = cb[c];
    #pragma unroll
    for (int k = 0; k < DCONV; k++) {
        int tt = t - (DCONV - 1) + k;
        if (tt >= 0)
            v = fmaf(g_xz[(size_t)tt * (2 * DINNER) + c], cw[c * DCONV + k], v);
    }
    g_u[i] = v / (1.f + expf(-v));   // silu
}

// ---------------- selective scan (fused with y-combine epilogue) ----------------
// lane layout: 2 channels per warp, 16 state-lanes per channel.
// h_{t} = exp(delta*A) * h_{t-1} + delta*u*B[t,s]; y[t,d] = sum_s h*C[t,s]
// fused tail: yf = (y + u*Dp) * silu(z)
__global__ void scan_kernel(const float* __restrict__ delta,
                            const float* __restrict__ u,
                            const float* __restrict__ xdbl,
                            const float* __restrict__ A_log,
                            const float* __restrict__ xz,
                            const float* __restrict__ Dp,
                            float* __restrict__ yf) {
    int warp = threadIdx.x >> 5;
    int lane = threadIdx.x & 31;
    int half = lane >> 4;
    int s    = lane & 15;
    int ch   = blockIdx.x * 8 + warp * 2 + half;

    float A2 = -__expf(A_log[ch * DSTATE + s]) * 1.44269504088896f;  // A * log2(e)
    float dpv = Dp[ch];
    float h = 0.f;
    const float* Bp = xdbl + DTRANK;            // B at cols [32,48)
    const float* Cp = xdbl + DTRANK + DSTATE;   // C at cols [48,64)

    for (int t0 = 0; t0 < LSEQ; t0 += 16) {
        float dv[16], uv[16], bv[16], cv[16];
        #pragma unroll
        for (int j = 0; j < 16; j++) {
            int t = t0 + j;
            dv[j] = delta[(size_t)t * DINNER + ch];
            uv[j] = u[(size_t)t * DINNER + ch];
            bv[j] = Bp[(size_t)t * XDIM + s];
            cv[j] = Cp[(size_t)t * XDIM + s];
        }
        float p[16];
        #pragma unroll
        for (int j = 0; j < 16; j++) {
            float dA  = exp2f(dv[j] * A2);
            float dbu = dv[j] * uv[j] * bv[j];
            h = fmaf(dA, h, dbu);
            p[j] = h * cv[j];
        }
        float out = 0.f;
        #pragma unroll
        for (int j = 0; j < 16; j++) {
            float v = p[j];
            v += __shfl_xor_sync(0xffffffffu, v, 1);
            v += __shfl_xor_sync(0xffffffffu, v, 2);
            v += __shfl_xor_sync(0xffffffffu, v, 4);
            v += __shfl_xor_sync(0xffffffffu, v, 8);
            if (s == j) out = v;
        }
        int t = t0 + s;
        float uo = u[(size_t)t * DINNER + ch];
        float zz = xz[(size_t)t * (2 * DINNER) + DINNER + ch];
        float sz = zz / (1.f + expf(-zz));
        yf[(size_t)t * DINNER + ch] = (out + uo * dpv) * sz;
    }
}

// ---------------- cross-entropy loss over logits ----------------
__global__ void loss_init_kernel() { g_loss[0] = 0.f; g_loss[1] = 0.f; }

__global__ void loss_kernel(const int* __restrict__ labels,
                            const float* __restrict__ logits) {
    int t = blockIdx.x;   // 0..L-2
    const float* row = logits + (size_t)t * VOCAB;
    float mx = -1e30f;
    for (int j = threadIdx.x; j < VOCAB; j += 256) mx = fmaxf(mx, row[j]);
    mx = blockReduceMax(mx);
    float sum = 0.f;
    for (int j = threadIdx.x; j < VOCAB; j += 256) sum += expf(row[j] - mx);
    sum = blockReduceSum(sum);
    if (threadIdx.x == 0) {
        int tgt = labels[t + 1];
        if (tgt != -100) {
            float lp = row[tgt] - mx - logf(sum);
            atomicAdd(&g_loss[0], -lp);
            atomicAdd(&g_loss[1], 1.f);
        }
    }
}

__global__ void loss_final_kernel(float* __restrict__ out, int idx) {
    out[idx] = g_loss[0] / fmaxf(g_loss[1], 1.f);
}

// ---------------- driver ----------------
extern "C" void kernel_launch(void* const* d_in, const int* in_sizes, int n_in,
                              void* d_out, int out_size) {
    const int*   ids    = (const int*)  d_in[0];
    const int*   labels = (const int*)  d_in[1];
    const float* emb    = (const float*)d_in[2];
    const float* pos    = (const float*)d_in[3];
    const float* fnw    = (const float*)d_in[4];
    const float* nw     = (const float*)d_in[5];
    const float* inw    = (const float*)d_in[6];
    const float* cw     = (const float*)d_in[7];
    const float* cb     = (const float*)d_in[8];
    const float* xw     = (const float*)d_in[9];
    const float* dw     = (const float*)d_in[10];
    const float* db     = (const float*)d_in[11];
    const float* alog   = (const float*)d_in[12];
    const float* dp     = (const float*)d_in[13];
    const float* ow     = (const float*)d_in[14];
    float* out = (float*)d_out;

    float *ph, *px, *pxz, *pu, *pxd, *pxpart, *pdelta, *pyf;
    cudaGetSymbolAddress((void**)&ph,     g_h);
    cudaGetSymbolAddress((void**)&px,     g_x);
    cudaGetSymbolAddress((void**)&pxz,    g_xz);
    cudaGetSymbolAddress((void**)&pu,     g_u);
    cudaGetSymbolAddress((void**)&pxd,    g_xdbl);
    cudaGetSymbolAddress((void**)&pxpart, g_xpart);
    cudaGetSymbolAddress((void**)&pdelta, g_delta);
    cudaGetSymbolAddress((void**)&pyf,    g_yf);

    embed_kernel<<<(LSEQ * DMODEL + 255) / 256, 256>>>(ids, emb, pos);

    for (int l = 0; l < NLAYER; l++) {
        const float* nw_l  = nw   + (size_t)l * DMODEL;
        const float* inw_l = inw  + (size_t)l * 2 * DINNER * DMODEL;
        const float* cw_l  = cw   + (size_t)l * DINNER * DCONV;
        const float* cb_l  = cb   + (size_t)l * DINNER;
        const float* xw_l  = xw   + (size_t)l * XDIM * DINNER;
        const float* dw_l  = dw   + (size_t)l * DINNER * DTRANK;
        const float* db_l  = db   + (size_t)l * DINNER;
        const float* al_l  = alog + (size_t)l * DINNER * DSTATE;
        const float* dp_l  = dp   + (size_t)l * DINNER;
        const float* ow_l  = ow   + (size_t)l * DMODEL * DINNER;

        // x = rmsnorm(h)
        rmsnorm_kernel<<<LSEQ, 256>>>(ph, nw_l, px);
        // xz = x @ in_w^T   [2048 x 2048], K=512
        gemm128_kernel<0><<<dim3(2 * DINNER / 128, LSEQ / 128), 256>>>(
            DMODEL, px, DMODEL, inw_l, DMODEL, pxz, 2 * DINNER, nullptr);
        // u = silu(causal depthwise conv(xi) + b)
        conv_silu_kernel<<<(LSEQ * DINNER + 255) / 256, 256>>>(cw_l, cb_l);
        // xdbl = u @ xproj_w^T  [2048 x 64], K=1024, split-K x4 (deterministic)
        gemm64_kernel<0><<<dim3(1, LSEQ / 64, 4), 256>>>(
            DINNER / 4, pu, DINNER, xw_l, DINNER, pxpart, XDIM, LSEQ * XDIM,
            nullptr, nullptr);
        reduce4_kernel<<<(LSEQ * XDIM + 255) / 256, 256>>>(pxd);
        // delta = softplus(dt @ dt_w^T + dt_b)  [2048 x 1024], K=32
        gemm64_kernel<1><<<dim3(DINNER / 64, LSEQ / 64), 256>>>(
            DTRANK, pxd, XDIM, dw_l, DTRANK, pdelta, DINNER, 0,
            db_l, nullptr);
        // selective scan + fused (y + u*Dp)*silu(z) -> yf
        scan_kernel<<<DINNER / 8, 128>>>(pdelta, pu, pxd, al_l, pxz, dp_l, pyf);
        // h = h + yf @ out_w^T  [2048 x 512], K=1024
        gemm64_kernel<2><<<dim3(DMODEL / 64, LSEQ / 64), 256>>>(
            DINNER, pyf, DINNER, ow_l, DINNER, ph, DMODEL, 0,
            nullptr, ph);
    }

    // final norm + logits
    rmsnorm_kernel<<<LSEQ, 256>>>(ph, fnw, px);
    gemm128_kernel<0><<<dim3(VOCAB / 128, LSEQ / 128), 256>>>(
        DMODEL, px, DMODEL, emb, DMODEL, out, VOCAB, nullptr);

    // loss
    loss_init_kernel<<<1, 1>>>();
    loss_kernel<<<LSEQ - 1, 256>>>(labels, out);
    loss_final_kernel<<<1, 1>>>(out, out_size - 1);
}

// round 5
// speedup vs baseline: 1.6416x; 1.0412x over previous
#include <cuda_runtime.h>
#include <cuda_bf16.h>
#include <math.h>
#include <stdint.h>

#define LSEQ   2048
#define DMODEL 512
#define NLAYER 8
#define DSTATE 16
#define DCONV  4
#define DINNER 1024
#define DTRANK 32
#define VOCAB  4096
#define XDIM   64   // DT_RANK + 2*D_STATE

// ---------------- scratch (static device globals; no allocation) ----------------
__device__ float g_h[LSEQ * DMODEL];
__device__ float g_xz[LSEQ * 2 * DINNER];
__device__ float g_u[LSEQ * DINNER];
__device__ float g_xdbl[LSEQ * XDIM];
__device__ float g_xpart[4 * LSEQ * XDIM];
__device__ float g_delta[LSEQ * DINNER];
__device__ float g_loss[2];

// bf16 hi/lo split buffers
__device__ __nv_bfloat16 g_a_h[LSEQ * DINNER];
__device__ __nv_bfloat16 g_a_l[LSEQ * DINNER];
__device__ __nv_bfloat16 g_wemb_h[VOCAB * DMODEL];
__device__ __nv_bfloat16 g_wemb_l[VOCAB * DMODEL];
__device__ __nv_bfloat16 g_win_h[NLAYER * 2 * DINNER * DMODEL];
__device__ __nv_bfloat16 g_win_l[NLAYER * 2 * DINNER * DMODEL];
__device__ __nv_bfloat16 g_wout_h[NLAYER * DMODEL * DINNER];
__device__ __nv_bfloat16 g_wout_l[NLAYER * DMODEL * DINNER];

// =============================== PTX helpers ===============================
__device__ __forceinline__ uint32_t smem_to_u32(const void* p) {
    uint32_t a;
    asm("{ .reg .u64 t; cvta.to.shared.u64 t, %1; cvt.u32.u64 %0, t; }"
        : "=r"(a) : "l"(p));
    return a;
}

#define CP_ASYNC_16(dst, src) \
    asm volatile("cp.async.cg.shared.global [%0], [%1], 16;" \
        :: "r"(dst), "l"(src) : "memory")
#define CP_ASYNC_COMMIT() asm volatile("cp.async.commit_group;" ::: "memory")
#define CP_ASYNC_WAIT0()  asm volatile("cp.async.wait_group 0;" ::: "memory")

__device__ __forceinline__ void ldmatrix_x4(uint32_t* r, uint32_t addr) {
    asm volatile("ldmatrix.sync.aligned.m8n8.x4.shared.b16 {%0,%1,%2,%3}, [%4];"
        : "=r"(r[0]), "=r"(r[1]), "=r"(r[2]), "=r"(r[3]) : "r"(addr));
}

__device__ __forceinline__ void mma16816(float* c, const uint32_t* a, const uint32_t* b) {
    asm volatile(
        "mma.sync.aligned.m16n8k16.row.col.f32.bf16.bf16.f32 "
        "{%0,%1,%2,%3}, {%4,%5,%6,%7}, {%8,%9}, {%0,%1,%2,%3};"
        : "+f"(c[0]), "+f"(c[1]), "+f"(c[2]), "+f"(c[3])
        : "r"(a[0]), "r"(a[1]), "r"(a[2]), "r"(a[3]), "r"(b[0]), "r"(b[1]));
}

// ======================= HMMA split-bf16 GEMM =======================
// C[M,N] = (Ah+Al)[M,K] * (Bh+Bl)[N,K]^T   (Al*Bl dropped)
// CTA tile 128x128, K chunks of 64, cp.async double-buffered smem.
// 256 threads = 8 warps (2 m x 4 n), warp tile 64x32.
// smem tile: 128 rows x 64 bf16, row stride 72 bf16 (144 B, ldmatrix conflict-free)
#define HT_STRIDE 72
#define HT_TILE_ELE (128 * HT_STRIDE)            // bf16 elems per tile
#define HT_BUF_ELE  (4 * HT_TILE_ELE)            // Ah,Al,Bh,Bl
#define HT_SMEM_BYTES (2 * HT_BUF_ELE * 2)       // double buffer, bytes

__device__ __forceinline__ void hmma_fill(
    uint32_t sdst,                // smem byte addr of tile base
    const __nv_bfloat16* __restrict__ g, int ld, int row0, int k0, int tid) {
    // 128 rows x 64 bf16 = 16384 B = 1024 x 16B transfers; 256 thr x 4 iters
    #pragma unroll
    for (int r = 0; r < 4; r++) {
        int idx = r * 256 + tid;          // 0..1023
        int row = idx >> 3, seg = idx & 7;
        uint32_t so = sdst + (uint32_t)(row * HT_STRIDE + seg * 8) * 2;
        const void* gp = g + (size_t)(row0 + row) * ld + k0 + seg * 8;
        CP_ASYNC_16(so, gp);
    }
}

// EPI: 0 = store, 2 = += resid
template <int EPI>
__global__ void __launch_bounds__(256, 1) gemm_hmma_kernel(
    int K,
    const __nv_bfloat16* __restrict__ Ah, const __nv_bfloat16* __restrict__ Al, int lda,
    const __nv_bfloat16* __restrict__ Bh, const __nv_bfloat16* __restrict__ Bl, int ldb,
    float* __restrict__ C, int ldc,
    const float* __restrict__ resid) {
    extern __shared__ __nv_bfloat16 smem[];
    const uint32_t sbu = smem_to_u32(smem);
    const int tid = threadIdx.x;
    const int wid = tid >> 5, lane = tid & 31;
    const int bm0 = blockIdx.y * 128, bn0 = blockIdx.x * 128;
    const int wm = (wid >> 2) * 64;      // warp row base in tile
    const int wn = (wid & 3) * 32;       // warp col base in tile

    float acc[4][4][4];
    #pragma unroll
    for (int i = 0; i < 4; i++)
        #pragma unroll
        for (int j = 0; j < 4; j++)
            #pragma unroll
            for (int q = 0; q < 4; q++) acc[i][j][q] = 0.f;

    const int NC = K >> 6;

    // prefetch chunk 0 into buffer 0
    {
        uint32_t b0 = sbu;
        hmma_fill(b0 + 0 * HT_TILE_ELE * 2, Ah, lda, bm0, 0, tid);
        hmma_fill(b0 + 1 * HT_TILE_ELE * 2, Al, lda, bm0, 0, tid);
        hmma_fill(b0 + 2 * HT_TILE_ELE * 2, Bh, ldb, bn0, 0, tid);
        hmma_fill(b0 + 3 * HT_TILE_ELE * 2, Bl, ldb, bn0, 0, tid);
        CP_ASYNC_COMMIT();
    }

    // ldmatrix lane address components (element units)
    const int a_row = ((lane >> 3) & 1) * 8 + (lane & 7);
    const int a_col = ((lane >> 4) & 1) * 8;
    const int b_row = ((lane >> 4) & 1) * 8 + (lane & 7);
    const int b_col = ((lane >> 3) & 1) * 8;

    for (int ck = 0; ck < NC; ck++) {
        const int b = ck & 1;
        CP_ASYNC_WAIT0();
        __syncthreads();
        if (ck + 1 < NC) {
            uint32_t nb = sbu + (uint32_t)((b ^ 1) * HT_BUF_ELE) * 2;
            const int k0 = (ck + 1) << 6;
            hmma_fill(nb + 0 * HT_TILE_ELE * 2, Ah, lda, bm0, k0, tid);
            hmma_fill(nb + 1 * HT_TILE_ELE * 2, Al, lda, bm0, k0, tid);
            hmma_fill(nb + 2 * HT_TILE_ELE * 2, Bh, ldb, bn0, k0, tid);
            hmma_fill(nb + 3 * HT_TILE_ELE * 2, Bl, ldb, bn0, k0, tid);
            CP_ASYNC_COMMIT();
        }

        const uint32_t sAh = sbu + (uint32_t)(b * HT_BUF_ELE + 0 * HT_TILE_ELE) * 2;
        const uint32_t sAl = sbu + (uint32_t)(b * HT_BUF_ELE + 1 * HT_TILE_ELE) * 2;
        const uint32_t sBh = sbu + (uint32_t)(b * HT_BUF_ELE + 2 * HT_TILE_ELE) * 2;
        const uint32_t sBl = sbu + (uint32_t)(b * HT_BUF_ELE + 3 * HT_TILE_ELE) * 2;

        #pragma unroll
        for (int kk = 0; kk < 4; kk++) {
            const int kc = kk * 16;
            uint32_t ah[4][4], al[4][4], bh[4][2], bl[4][2];
            #pragma unroll
            for (int mt = 0; mt < 4; mt++) {
                uint32_t off = (uint32_t)((wm + mt * 16 + a_row) * HT_STRIDE + kc + a_col) * 2;
                ldmatrix_x4(ah[mt], sAh + off);
                ldmatrix_x4(al[mt], sAl + off);
            }
            #pragma unroll
            for (int nt2 = 0; nt2 < 2; nt2++) {
                uint32_t off = (uint32_t)((wn + nt2 * 16 + b_row) * HT_STRIDE + kc + b_col) * 2;
                uint32_t r[4];
                ldmatrix_x4(r, sBh + off);
                bh[nt2 * 2][0] = r[0]; bh[nt2 * 2][1] = r[1];
                bh[nt2 * 2 + 1][0] = r[2]; bh[nt2 * 2 + 1][1] = r[3];
                ldmatrix_x4(r, sBl + off);
                bl[nt2 * 2][0] = r[0]; bl[nt2 * 2][1] = r[1];
                bl[nt2 * 2 + 1][0] = r[2]; bl[nt2 * 2 + 1][1] = r[3];
            }
            #pragma unroll
            for (int mt = 0; mt < 4; mt++)
                #pragma unroll
                for (int nt = 0; nt < 4; nt++) {
                    mma16816(acc[mt][nt], ah[mt], bh[nt]);
                    mma16816(acc[mt][nt], ah[mt], bl[nt]);
                    mma16816(acc[mt][nt], al[mt], bh[nt]);
                }
        }
        __syncthreads();
    }

    // epilogue: c0,c1 -> (row=lane>>2, col=(lane&3)*2); c2,c3 -> row+8
    const int er = lane >> 2, ec = (lane & 3) * 2;
    #pragma unroll
    for (int mt = 0; mt < 4; mt++) {
        #pragma unroll
        for (int nt = 0; nt < 4; nt++) {
            int row = bm0 + wm + mt * 16 + er;
            int col = bn0 + wn + nt * 8 + ec;
            float2 v0 = make_float2(acc[mt][nt][0], acc[mt][nt][1]);
            float2 v1 = make_float2(acc[mt][nt][2], acc[mt][nt][3]);
            if (EPI == 2) {
                const float2 r0 = *reinterpret_cast<const float2*>(
                    resid + (size_t)row * ldc + col);
                const float2 r1 = *reinterpret_cast<const float2*>(
                    resid + (size_t)(row + 8) * ldc + col);
                v0.x += r0.x; v0.y += r0.y;
                v1.x += r1.x; v1.y += r1.y;
            }
            *reinterpret_cast<float2*>(C + (size_t)row * ldc + col) = v0;
            *reinterpret_cast<float2*>(C + (size_t)(row + 8) * ldc + col) = v1;
        }
    }
}

// ---------------- fp32 -> bf16 hi/lo conversion ----------------
__global__ void cvt_kernel(const float* __restrict__ src,
                           __nv_bfloat16* __restrict__ hi,
                           __nv_bfloat16* __restrict__ lo, int n) {
    int i = (blockIdx.x * blockDim.x + threadIdx.x) * 4;
    if (i >= n) return;
    float4 v = *reinterpret_cast<const float4*>(src + i);
    __nv_bfloat16 h0 = __float2bfloat16(v.x), h1 = __float2bfloat16(v.y);
    __nv_bfloat16 h2 = __float2bfloat16(v.z), h3 = __float2bfloat16(v.w);
    __nv_bfloat16 l0 = __float2bfloat16(v.x - __bfloat162float(h0));
    __nv_bfloat16 l1 = __float2bfloat16(v.y - __bfloat162float(h1));
    __nv_bfloat16 l2 = __float2bfloat16(v.z - __bfloat162float(h2));
    __nv_bfloat16 l3 = __float2bfloat16(v.w - __bfloat162float(h3));
    *reinterpret_cast<__nv_bfloat162*>(hi + i)     = __halves2bfloat162(h0, h1);
    *reinterpret_cast<__nv_bfloat162*>(hi + i + 2) = __halves2bfloat162(h2, h3);
    *reinterpret_cast<__nv_bfloat162*>(lo + i)     = __halves2bfloat162(l0, l1);
    *reinterpret_cast<__nv_bfloat162*>(lo + i + 2) = __halves2bfloat162(l2, l3);
}

// ---------------- block reductions ----------------
__device__ __forceinline__ float blockReduceSum(float v) {
    __shared__ float sh[9];
    int lane = threadIdx.x & 31, w = threadIdx.x >> 5;
    #pragma unroll
    for (int o = 16; o; o >>= 1) v += __shfl_xor_sync(0xffffffffu, v, o);
    if (lane == 0) sh[w] = v;
    __syncthreads();
    if (threadIdx.x == 0) {
        float s = 0.f;
        int nw = (blockDim.x + 31) >> 5;
        for (int i = 0; i < nw; i++) s += sh[i];
        sh[8] = s;
    }
    __syncthreads();
    float r = sh[8];
    __syncthreads();
    return r;
}

__device__ __forceinline__ float blockReduceMax(float v) {
    __shared__ float sh[9];
    int lane = threadIdx.x & 31, w = threadIdx.x >> 5;
    #pragma unroll
    for (int o = 16; o; o >>= 1) v = fmaxf(v, __shfl_xor_sync(0xffffffffu, v, o));
    if (lane == 0) sh[w] = v;
    __syncthreads();
    if (threadIdx.x == 0) {
        float s = -1e30f;
        int nw = (blockDim.x + 31) >> 5;
        for (int i = 0; i < nw; i++) s = fmaxf(s, sh[i]);
        sh[8] = s;
    }
    __syncthreads();
    float r = sh[8];
    __syncthreads();
    return r;
}

// ---------------- embedding ----------------
__global__ void embed_kernel(const int* __restrict__ ids,
                             const float* __restrict__ emb,
                             const float* __restrict__ pos) {
    int i = blockIdx.x * blockDim.x + threadIdx.x;
    if (i >= LSEQ * DMODEL) return;
    int t = i / DMODEL;
    int d = i - t * DMODEL;
    g_h[i] = emb[(size_t)ids[t] * DMODEL + d] + pos[i];
}

// ---------------- rmsnorm -> bf16 hi/lo ----------------
__global__ void rmsnorm_kernel(const float* __restrict__ src,
                               const float* __restrict__ w,
                               __nv_bfloat16* __restrict__ dh,
                               __nv_bfloat16* __restrict__ dl) {
    int t = blockIdx.x;
    const float* r = src + (size_t)t * DMODEL;
    float v0 = r[threadIdx.x];
    float v1 = r[threadIdx.x + 256];
    float ss = blockReduceSum(v0 * v0 + v1 * v1);
    float sc = rsqrtf(ss * (1.0f / DMODEL) + 1e-6f);
    float o0 = v0 * sc * w[threadIdx.x];
    float o1 = v1 * sc * w[threadIdx.x + 256];
    size_t base = (size_t)t * DMODEL;
    __nv_bfloat16 h0 = __float2bfloat16(o0);
    __nv_bfloat16 h1 = __float2bfloat16(o1);
    dh[base + threadIdx.x]       = h0;
    dh[base + threadIdx.x + 256] = h1;
    dl[base + threadIdx.x]       = __float2bfloat16(o0 - __bfloat162float(h0));
    dl[base + threadIdx.x + 256] = __float2bfloat16(o1 - __bfloat162float(h1));
}

// =================================================================================
// fp32 GEMM 64x64x16 (small xproj/dt), double-buffered, 256 threads, 4x4/thread
// split-K via blockIdx.z. EPI: 0 = store, 1 = softplus(v+bias[col])
// =================================================================================
template <int EPI>
__global__ void __launch_bounds__(256) gemm64_kernel(
    int Kloc,
    const float* __restrict__ A, int lda,
    const float* __restrict__ B, int ldb,
    float* __restrict__ C, int ldc, int partStride,
    const float* __restrict__ bias) {
    __shared__ float As[2][16][68];
    __shared__ float Bs[2][16][68];
    const int tid = threadIdx.x;
    const int bm0 = blockIdx.y * 64, bn0 = blockIdx.x * 64;
    const int kbase = blockIdx.z * Kloc;
    C += (size_t)blockIdx.z * partStride;

    const int lrow = tid >> 2;
    const int kq0  = (tid & 3) << 2;
    const float* Ap = A + (size_t)(bm0 + lrow) * lda + kbase + kq0;
    const float* Bp = B + (size_t)(bn0 + lrow) * ldb + kbase + kq0;

    const int ty = tid >> 4, tx = tid & 15;

    float acc[4][4];
    #pragma unroll
    for (int i = 0; i < 4; i++)
        #pragma unroll
        for (int j = 0; j < 4; j++) acc[i][j] = 0.f;

    float4 av = *reinterpret_cast<const float4*>(Ap);
    float4 bv = *reinterpret_cast<const float4*>(Bp);
    As[0][kq0 + 0][lrow] = av.x; As[0][kq0 + 1][lrow] = av.y;
    As[0][kq0 + 2][lrow] = av.z; As[0][kq0 + 3][lrow] = av.w;
    Bs[0][kq0 + 0][lrow] = bv.x; Bs[0][kq0 + 1][lrow] = bv.y;
    Bs[0][kq0 + 2][lrow] = bv.z; Bs[0][kq0 + 3][lrow] = bv.w;
    __syncthreads();

    const int KT = Kloc >> 4;
    for (int kt = 0; kt < KT; kt++) {
        const int cur = kt & 1, nxt = cur ^ 1;
        if (kt + 1 < KT) {
            int off = (kt + 1) << 4;
            av = *reinterpret_cast<const float4*>(Ap + off);
            bv = *reinterpret_cast<const float4*>(Bp + off);
        }
        #pragma unroll
        for (int kk = 0; kk < 16; kk++) {
            float4 a4 = *reinterpret_cast<const float4*>(&As[cur][kk][ty * 4]);
            float4 b4 = *reinterpret_cast<const float4*>(&Bs[cur][kk][tx * 4]);
            float a[4] = {a4.x, a4.y, a4.z, a4.w};
            float b[4] = {b4.x, b4.y, b4.z, b4.w};
            #pragma unroll
            for (int i = 0; i < 4; i++)
                #pragma unroll
                for (int j = 0; j < 4; j++)
                    acc[i][j] = fmaf(a[i], b[j], acc[i][j]);
        }
        if (kt + 1 < KT) {
            As[nxt][kq0 + 0][lrow] = av.x; As[nxt][kq0 + 1][lrow] = av.y;
            As[nxt][kq0 + 2][lrow] = av.z; As[nxt][kq0 + 3][lrow] = av.w;
            Bs[nxt][kq0 + 0][lrow] = bv.x; Bs[nxt][kq0 + 1][lrow] = bv.y;
            Bs[nxt][kq0 + 2][lrow] = bv.z; Bs[nxt][kq0 + 3][lrow] = bv.w;
            __syncthreads();
        }
    }

    float4 bias4;
    if (EPI == 1) bias4 = *reinterpret_cast<const float4*>(&bias[bn0 + tx * 4]);

    #pragma unroll
    for (int i = 0; i < 4; i++) {
        int row = bm0 + ty * 4 + i;
        float* cp = C + (size_t)row * ldc + bn0 + tx * 4;
        float4 v = make_float4(acc[i][0], acc[i][1], acc[i][2], acc[i][3]);
        if (EPI == 1) {
            v.x += bias4.x; v.y += bias4.y; v.z += bias4.z; v.w += bias4.w;
            v.x = (v.x > 20.f) ? v.x : log1pf(expf(v.x));
            v.y = (v.y > 20.f) ? v.y : log1pf(expf(v.y));
            v.z = (v.z > 20.f) ? v.z : log1pf(expf(v.z));
            v.w = (v.w > 20.f) ? v.w : log1pf(expf(v.w));
        }
        *reinterpret_cast<float4*>(cp) = v;
    }
}

// ---------------- reduce the 4 split-K partials of xproj ----------------
__global__ void reduce4_kernel(float* __restrict__ dst) {
    int i = blockIdx.x * blockDim.x + threadIdx.x;
    if (i >= LSEQ * XDIM) return;
    dst[i] = g_xpart[i] + g_xpart[i + LSEQ * XDIM]
           + g_xpart[i + 2 * LSEQ * XDIM] + g_xpart[i + 3 * LSEQ * XDIM];
}

// ---------------- depthwise causal conv (width 4) + bias + silu ----------------
__global__ void conv_silu_kernel(const float* __restrict__ cw,
                                 const float* __restrict__ cb) {
    int i = blockIdx.x * blockDim.x + threadIdx.x;
    if (i >= LSEQ * DINNER) return;
    int c = i & (DINNER - 1);
    int t = i >> 10;
    float v = cb[c];
    #pragma unroll
    for (int k = 0; k < DCONV; k++) {
        int tt = t - (DCONV - 1) + k;
        if (tt >= 0)
            v = fmaf(g_xz[(size_t)tt * (2 * DINNER) + c], cw[c * DCONV + k], v);
    }
    g_u[i] = v / (1.f + expf(-v));   // silu
}

// ---------------- selective scan (fused y-combine, emits bf16 hi/lo) ----------------
__global__ void scan_kernel(const float* __restrict__ delta,
                            const float* __restrict__ u,
                            const float* __restrict__ xdbl,
                            const float* __restrict__ A_log,
                            const float* __restrict__ xz,
                            const float* __restrict__ Dp,
                            __nv_bfloat16* __restrict__ yh,
                            __nv_bfloat16* __restrict__ yl) {
    int warp = threadIdx.x >> 5;
    int lane = threadIdx.x & 31;
    int half = lane >> 4;
    int s    = lane & 15;
    int ch   = blockIdx.x * 8 + warp * 2 + half;

    float A2 = -__expf(A_log[ch * DSTATE + s]) * 1.44269504088896f;
    float dpv = Dp[ch];
    float h = 0.f;
    const float* Bp = xdbl + DTRANK;
    const float* Cp = xdbl + DTRANK + DSTATE;

    for (int t0 = 0; t0 < LSEQ; t0 += 16) {
        float dv[16], uv[16], bv[16], cv[16];
        #pragma unroll
        for (int j = 0; j < 16; j++) {
            int t = t0 + j;
            dv[j] = delta[(size_t)t * DINNER + ch];
            uv[j] = u[(size_t)t * DINNER + ch];
            bv[j] = Bp[(size_t)t * XDIM + s];
            cv[j] = Cp[(size_t)t * XDIM + s];
        }
        float p[16];
        #pragma unroll
        for (int j = 0; j < 16; j++) {
            float dA  = exp2f(dv[j] * A2);
            float dbu = dv[j] * uv[j] * bv[j];
            h = fmaf(dA, h, dbu);
            p[j] = h * cv[j];
        }
        float out = 0.f;
        #pragma unroll
        for (int j = 0; j < 16; j++) {
            float v = p[j];
            v += __shfl_xor_sync(0xffffffffu, v, 1);
            v += __shfl_xor_sync(0xffffffffu, v, 2);
            v += __shfl_xor_sync(0xffffffffu, v, 4);
            v += __shfl_xor_sync(0xffffffffu, v, 8);
            if (s == j) out = v;
        }
        int t = t0 + s;
        float uo = u[(size_t)t * DINNER + ch];
        float zz = xz[(size_t)t * (2 * DINNER) + DINNER + ch];
        float sz = zz / (1.f + expf(-zz));
        float val = (out + uo * dpv) * sz;
        __nv_bfloat16 hh = __float2bfloat16(val);
        yh[(size_t)t * DINNER + ch] = hh;
        yl[(size_t)t * DINNER + ch] = __float2bfloat16(val - __bfloat162float(hh));
    }
}

// ---------------- cross-entropy loss over logits ----------------
__global__ void loss_init_kernel() { g_loss[0] = 0.f; g_loss[1] = 0.f; }

__global__ void loss_kernel(const int* __restrict__ labels,
                            const float* __restrict__ logits) {
    int t = blockIdx.x;
    const float* row = logits + (size_t)t * VOCAB;
    float mx = -1e30f;
    for (int j = threadIdx.x; j < VOCAB; j += 256) mx = fmaxf(mx, row[j]);
    mx = blockReduceMax(mx);
    float sum = 0.f;
    for (int j = threadIdx.x; j < VOCAB; j += 256) sum += expf(row[j] - mx);
    sum = blockReduceSum(sum);
    if (threadIdx.x == 0) {
        int tgt = labels[t + 1];
        if (tgt != -100) {
            float lp = row[tgt] - mx - logf(sum);
            atomicAdd(&g_loss[0], -lp);
            atomicAdd(&g_loss[1], 1.f);
        }
    }
}

__global__ void loss_final_kernel(float* __restrict__ out, int idx) {
    out[idx] = g_loss[0] / fmaxf(g_loss[1], 1.f);
}

// ---------------- driver ----------------
extern "C" void kernel_launch(void* const* d_in, const int* in_sizes, int n_in,
                              void* d_out, int out_size) {
    const int*   ids    = (const int*)  d_in[0];
    const int*   labels = (const int*)  d_in[1];
    const float* emb    = (const float*)d_in[2];
    const float* pos    = (const float*)d_in[3];
    const float* fnw    = (const float*)d_in[4];
    const float* nw     = (const float*)d_in[5];
    const float* inw    = (const float*)d_in[6];
    const float* cw     = (const float*)d_in[7];
    const float* cb     = (const float*)d_in[8];
    const float* xw     = (const float*)d_in[9];
    const float* dw     = (const float*)d_in[10];
    const float* db     = (const float*)d_in[11];
    const float* alog   = (const float*)d_in[12];
    const float* dp     = (const float*)d_in[13];
    const float* ow     = (const float*)d_in[14];
    float* out = (float*)d_out;

    float *ph, *pxz, *pu, *pxd, *pxpart, *pdelta;
    __nv_bfloat16 *pah, *pal, *pweh, *pwel, *pwih, *pwil, *pwoh, *pwol;
    cudaGetSymbolAddress((void**)&ph,     g_h);
    cudaGetSymbolAddress((void**)&pxz,    g_xz);
    cudaGetSymbolAddress((void**)&pu,     g_u);
    cudaGetSymbolAddress((void**)&pxd,    g_xdbl);
    cudaGetSymbolAddress((void**)&pxpart, g_xpart);
    cudaGetSymbolAddress((void**)&pdelta, g_delta);
    cudaGetSymbolAddress((void**)&pah,    g_a_h);
    cudaGetSymbolAddress((void**)&pal,    g_a_l);
    cudaGetSymbolAddress((void**)&pweh,   g_wemb_h);
    cudaGetSymbolAddress((void**)&pwel,   g_wemb_l);
    cudaGetSymbolAddress((void**)&pwih,   g_win_h);
    cudaGetSymbolAddress((void**)&pwil,   g_win_l);
    cudaGetSymbolAddress((void**)&pwoh,   g_wout_h);
    cudaGetSymbolAddress((void**)&pwol,   g_wout_l);

    cudaFuncSetAttribute(gemm_hmma_kernel<0>,
        cudaFuncAttributeMaxDynamicSharedMemorySize, HT_SMEM_BYTES);
    cudaFuncSetAttribute(gemm_hmma_kernel<2>,
        cudaFuncAttributeMaxDynamicSharedMemorySize, HT_SMEM_BYTES);

    // convert weights to bf16 hi/lo
    cvt_kernel<<<(VOCAB * DMODEL / 4 + 255) / 256, 256>>>(emb, pweh, pwel, VOCAB * DMODEL);
    cvt_kernel<<<(NLAYER * 2 * DINNER * DMODEL / 4 + 255) / 256, 256>>>(
        inw, pwih, pwil, NLAYER * 2 * DINNER * DMODEL);
    cvt_kernel<<<(NLAYER * DMODEL * DINNER / 4 + 255) / 256, 256>>>(
        ow, pwoh, pwol, NLAYER * DMODEL * DINNER);

    embed_kernel<<<(LSEQ * DMODEL + 255) / 256, 256>>>(ids, emb, pos);

    for (int l = 0; l < NLAYER; l++) {
        const float* nw_l  = nw   + (size_t)l * DMODEL;
        const float* cw_l  = cw   + (size_t)l * DINNER * DCONV;
        const float* cb_l  = cb   + (size_t)l * DINNER;
        const float* xw_l  = xw   + (size_t)l * XDIM * DINNER;
        const float* dw_l  = dw   + (size_t)l * DINNER * DTRANK;
        const float* db_l  = db   + (size_t)l * DINNER;
        const float* al_l  = alog + (size_t)l * DINNER * DSTATE;
        const float* dp_l  = dp   + (size_t)l * DINNER;
        const __nv_bfloat16* wih_l = pwih + (size_t)l * 2 * DINNER * DMODEL;
        const __nv_bfloat16* wil_l = pwil + (size_t)l * 2 * DINNER * DMODEL;
        const __nv_bfloat16* woh_l = pwoh + (size_t)l * DMODEL * DINNER;
        const __nv_bfloat16* wol_l = pwol + (size_t)l * DMODEL * DINNER;

        // x = rmsnorm(h) -> bf16 hi/lo
        rmsnorm_kernel<<<LSEQ, 256>>>(ph, nw_l, pah, pal);
        // xz = x @ in_w^T  [2048 x 2048], K=512 (HMMA)
        gemm_hmma_kernel<0><<<dim3(2 * DINNER / 128, LSEQ / 128), 256, HT_SMEM_BYTES>>>(
            DMODEL, pah, pal, DMODEL, wih_l, wil_l, DMODEL, pxz, 2 * DINNER, nullptr);
        // u = silu(causal depthwise conv(xi) + b)
        conv_silu_kernel<<<(LSEQ * DINNER + 255) / 256, 256>>>(cw_l, cb_l);
        // xdbl = u @ xproj_w^T  [2048 x 64], K=1024, split-K x4 (fp32)
        gemm64_kernel<0><<<dim3(1, LSEQ / 64, 4), 256>>>(
            DINNER / 4, pu, DINNER, xw_l, DINNER, pxpart, XDIM, LSEQ * XDIM, nullptr);
        reduce4_kernel<<<(LSEQ * XDIM + 255) / 256, 256>>>(pxd);
        // delta = softplus(dt @ dt_w^T + dt_b)  [2048 x 1024], K=32 (fp32)
        gemm64_kernel<1><<<dim3(DINNER / 64, LSEQ / 64), 256>>>(
            DTRANK, pxd, XDIM, dw_l, DTRANK, pdelta, DINNER, 0, db_l);
        // selective scan + fused (y + u*Dp)*silu(z) -> bf16 hi/lo
        scan_kernel<<<DINNER / 8, 128>>>(pdelta, pu, pxd, al_l, pxz, dp_l, pah, pal);
        // h = h + yf @ out_w^T  [2048 x 512], K=1024 (HMMA)
        gemm_hmma_kernel<2><<<dim3(DMODEL / 128, LSEQ / 128), 256, HT_SMEM_BYTES>>>(
            DINNER, pah, pal, DINNER, woh_l, wol_l, DINNER, ph, DMODEL, ph);
    }

    // final norm + logits (HMMA)
    rmsnorm_kernel<<<LSEQ, 256>>>(ph, fnw, pah, pal);
    gemm_hmma_kernel<0><<<dim3(VOCAB / 128, LSEQ / 128), 256, HT_SMEM_BYTES>>>(
        DMODEL, pah, pal, DMODEL, pweh, pwel, DMODEL, out, VOCAB, nullptr);

    // loss
    loss_init_kernel<<<1, 1>>>();
    loss_kernel<<<LSEQ - 1, 256>>>(labels, out);
    loss_final_kernel<<<1, 1>>>(out, out_size - 1);
}

// round 6
// speedup vs baseline: 2.3250x; 1.4163x over previous
#include <cuda_runtime.h>
#include <cuda_fp16.h>
#include <math.h>
#include <stdint.h>

#define LSEQ   2048
#define DMODEL 512
#define NLAYER 8
#define DSTATE 16
#define DCONV  4
#define DINNER 1024
#define DTRANK 32
#define VOCAB  4096
#define XDIM   64   // DT_RANK + 2*D_STATE

// ---------------- scratch (static device globals; no allocation) ----------------
__device__ float g_h[LSEQ * DMODEL];
__device__ float g_xz[LSEQ * 2 * DINNER];
__device__ float g_u[LSEQ * DINNER];
__device__ float g_xdbl[LSEQ * XDIM];
__device__ float g_xpart[4 * LSEQ * XDIM];
__device__ float g_delta[LSEQ * DINNER];
__device__ float g_loss[2];

// fp16 buffers
__device__ __half g_a16[LSEQ * DINNER];
__device__ __half g_wemb16[VOCAB * DMODEL];
__device__ __half g_win16[NLAYER * 2 * DINNER * DMODEL];
__device__ __half g_wout16[NLAYER * DMODEL * DINNER];

// =============================== PTX helpers ===============================
__device__ __forceinline__ uint32_t smem_to_u32(const void* p) {
    uint32_t a;
    asm("{ .reg .u64 t; cvta.to.shared.u64 t, %1; cvt.u32.u64 %0, t; }"
        : "=r"(a) : "l"(p));
    return a;
}

#define CP_ASYNC_16(dst, src) \
    asm volatile("cp.async.cg.shared.global [%0], [%1], 16;" \
        :: "r"(dst), "l"(src) : "memory")
#define CP_ASYNC_COMMIT() asm volatile("cp.async.commit_group;" ::: "memory")
#define CP_ASYNC_WAIT0()  asm volatile("cp.async.wait_group 0;" ::: "memory")

__device__ __forceinline__ void ldmatrix_x4(uint32_t* r, uint32_t addr) {
    asm volatile("ldmatrix.sync.aligned.m8n8.x4.shared.b16 {%0,%1,%2,%3}, [%4];"
        : "=r"(r[0]), "=r"(r[1]), "=r"(r[2]), "=r"(r[3]) : "r"(addr));
}

__device__ __forceinline__ void mma16816(float* c, const uint32_t* a, const uint32_t* b) {
    asm volatile(
        "mma.sync.aligned.m16n8k16.row.col.f32.f16.f16.f32 "
        "{%0,%1,%2,%3}, {%4,%5,%6,%7}, {%8,%9}, {%0,%1,%2,%3};"
        : "+f"(c[0]), "+f"(c[1]), "+f"(c[2]), "+f"(c[3])
        : "r"(a[0]), "r"(a[1]), "r"(a[2]), "r"(a[3]), "r"(b[0]), "r"(b[1]));
}

// ======================= fp16 HMMA GEMM =======================
// C[M,N] = A[M,K] * B[N,K]^T, fp16 inputs, fp32 accumulate.
// CTA tile 128x128, K chunks of 128, cp.async double-buffered smem.
// 256 threads = 8 warps (2 m x 4 n), warp tile 64x32.
// smem tile: 128 rows x 128 fp16, row stride 136 (272 B: rows hit distinct
// 16B segs mod 128B -> ldmatrix conflict-free)
#define HT_STRIDE 136
#define HT_TILE_ELE (128 * HT_STRIDE)
#define HT_BUF_ELE  (2 * HT_TILE_ELE)            // A, B
#define HT_SMEM_BYTES (2 * HT_BUF_ELE * 2)       // double buffer, bytes (136 KB)

__device__ __forceinline__ void hmma_fill(
    uint32_t sdst, const __half* __restrict__ g, int ld, int row0, int k0, int tid) {
    // 128 rows x 128 fp16 = 32768 B = 2048 x 16B transfers; 256 thr x 8 iters
    #pragma unroll
    for (int r = 0; r < 8; r++) {
        int idx = r * 256 + tid;          // 0..2047
        int row = idx >> 4, seg = idx & 15;
        uint32_t so = sdst + (uint32_t)(row * HT_STRIDE + seg * 8) * 2;
        const void* gp = g + (size_t)(row0 + row) * ld + k0 + seg * 8;
        CP_ASYNC_16(so, gp);
    }
}

// EPI: 0 = store, 2 = += resid
template <int EPI>
__global__ void __launch_bounds__(256, 1) gemm_hmma_kernel(
    int K,
    const __half* __restrict__ A, int lda,
    const __half* __restrict__ B, int ldb,
    float* __restrict__ C, int ldc,
    const float* __restrict__ resid) {
    extern __shared__ __half smem[];
    const uint32_t sbu = smem_to_u32(smem);
    const int tid = threadIdx.x;
    const int wid = tid >> 5, lane = tid & 31;
    const int bm0 = blockIdx.y * 128, bn0 = blockIdx.x * 128;
    const int wm = (wid >> 2) * 64;      // warp row base in tile
    const int wn = (wid & 3) * 32;       // warp col base in tile

    float acc[4][4][4];
    #pragma unroll
    for (int i = 0; i < 4; i++)
        #pragma unroll
        for (int j = 0; j < 4; j++)
            #pragma unroll
            for (int q = 0; q < 4; q++) acc[i][j][q] = 0.f;

    const int NC = K >> 7;

    // prefetch chunk 0 into buffer 0
    hmma_fill(sbu,                      A, lda, bm0, 0, tid);
    hmma_fill(sbu + HT_TILE_ELE * 2,    B, ldb, bn0, 0, tid);
    CP_ASYNC_COMMIT();

    // ldmatrix lane address components (element units)
    const int a_row = ((lane >> 3) & 1) * 8 + (lane & 7);
    const int a_col = ((lane >> 4) & 1) * 8;
    const int b_row = ((lane >> 4) & 1) * 8 + (lane & 7);
    const int b_col = ((lane >> 3) & 1) * 8;

    for (int ck = 0; ck < NC; ck++) {
        const int b = ck & 1;
        CP_ASYNC_WAIT0();
        __syncthreads();
        if (ck + 1 < NC) {
            uint32_t nb = sbu + (uint32_t)((b ^ 1) * HT_BUF_ELE) * 2;
            const int k0 = (ck + 1) << 7;
            hmma_fill(nb,                   A, lda, bm0, k0, tid);
            hmma_fill(nb + HT_TILE_ELE * 2, B, ldb, bn0, k0, tid);
            CP_ASYNC_COMMIT();
        }

        const uint32_t sA = sbu + (uint32_t)(b * HT_BUF_ELE) * 2;
        const uint32_t sB = sA + (uint32_t)HT_TILE_ELE * 2;

        #pragma unroll
        for (int kk = 0; kk < 8; kk++) {
            const int kc = kk * 16;
            uint32_t ah[4][4], bh[4][2];
            #pragma unroll
            for (int mt = 0; mt < 4; mt++) {
                uint32_t off = (uint32_t)((wm + mt * 16 + a_row) * HT_STRIDE + kc + a_col) * 2;
                ldmatrix_x4(ah[mt], sA + off);
            }
            #pragma unroll
            for (int nt2 = 0; nt2 < 2; nt2++) {
                uint32_t off = (uint32_t)((wn + nt2 * 16 + b_row) * HT_STRIDE + kc + b_col) * 2;
                uint32_t r[4];
                ldmatrix_x4(r, sB + off);
                bh[nt2 * 2][0] = r[0]; bh[nt2 * 2][1] = r[1];
                bh[nt2 * 2 + 1][0] = r[2]; bh[nt2 * 2 + 1][1] = r[3];
            }
            #pragma unroll
            for (int mt = 0; mt < 4; mt++)
                #pragma unroll
                for (int nt = 0; nt < 4; nt++)
                    mma16816(acc[mt][nt], ah[mt], bh[nt]);
        }
        __syncthreads();
    }

    // epilogue: c0,c1 -> (row=lane>>2, col=(lane&3)*2); c2,c3 -> row+8
    const int er = lane >> 2, ec = (lane & 3) * 2;
    #pragma unroll
    for (int mt = 0; mt < 4; mt++) {
        #pragma unroll
        for (int nt = 0; nt < 4; nt++) {
            int row = bm0 + wm + mt * 16 + er;
            int col = bn0 + wn + nt * 8 + ec;
            float2 v0 = make_float2(acc[mt][nt][0], acc[mt][nt][1]);
            float2 v1 = make_float2(acc[mt][nt][2], acc[mt][nt][3]);
            if (EPI == 2) {
                const float2 r0 = *reinterpret_cast<const float2*>(
                    resid + (size_t)row * ldc + col);
                const float2 r1 = *reinterpret_cast<const float2*>(
                    resid + (size_t)(row + 8) * ldc + col);
                v0.x += r0.x; v0.y += r0.y;
                v1.x += r1.x; v1.y += r1.y;
            }
            *reinterpret_cast<float2*>(C + (size_t)row * ldc + col) = v0;
            *reinterpret_cast<float2*>(C + (size_t)(row + 8) * ldc + col) = v1;
        }
    }
}

// ---------------- fp32 -> fp16 conversion ----------------
__global__ void cvt_kernel(const float* __restrict__ src,
                           __half* __restrict__ dst, int n) {
    int i = (blockIdx.x * blockDim.x + threadIdx.x) * 4;
    if (i >= n) return;
    float4 v = *reinterpret_cast<const float4*>(src + i);
    __half2 h0 = __floats2half2_rn(v.x, v.y);
    __half2 h1 = __floats2half2_rn(v.z, v.w);
    *reinterpret_cast<__half2*>(dst + i)     = h0;
    *reinterpret_cast<__half2*>(dst + i + 2) = h1;
}

// ---------------- block reductions ----------------
__device__ __forceinline__ float blockReduceSum(float v) {
    __shared__ float sh[9];
    int lane = threadIdx.x & 31, w = threadIdx.x >> 5;
    #pragma unroll
    for (int o = 16; o; o >>= 1) v += __shfl_xor_sync(0xffffffffu, v, o);
    if (lane == 0) sh[w] = v;
    __syncthreads();
    if (threadIdx.x == 0) {
        float s = 0.f;
        int nw = (blockDim.x + 31) >> 5;
        for (int i = 0; i < nw; i++) s += sh[i];
        sh[8] = s;
    }
    __syncthreads();
    float r = sh[8];
    __syncthreads();
    return r;
}

__device__ __forceinline__ float blockReduceMax(float v) {
    __shared__ float sh[9];
    int lane = threadIdx.x & 31, w = threadIdx.x >> 5;
    #pragma unroll
    for (int o = 16; o; o >>= 1) v = fmaxf(v, __shfl_xor_sync(0xffffffffu, v, o));
    if (lane == 0) sh[w] = v;
    __syncthreads();
    if (threadIdx.x == 0) {
        float s = -1e30f;
        int nw = (blockDim.x + 31) >> 5;
        for (int i = 0; i < nw; i++) s = fmaxf(s, sh[i]);
        sh[8] = s;
    }
    __syncthreads();
    float r = sh[8];
    __syncthreads();
    return r;
}

// ---------------- embedding ----------------
__global__ void embed_kernel(const int* __restrict__ ids,
                             const float* __restrict__ emb,
                             const float* __restrict__ pos) {
    int i = blockIdx.x * blockDim.x + threadIdx.x;
    if (i >= LSEQ * DMODEL) return;
    int t = i / DMODEL;
    int d = i - t * DMODEL;
    g_h[i] = emb[(size_t)ids[t] * DMODEL + d] + pos[i];
}

// ---------------- rmsnorm -> fp16 ----------------
__global__ void rmsnorm_kernel(const float* __restrict__ src,
                               const float* __restrict__ w,
                               __half* __restrict__ dst) {
    int t = blockIdx.x;
    const float* r = src + (size_t)t * DMODEL;
    float v0 = r[threadIdx.x];
    float v1 = r[threadIdx.x + 256];
    float ss = blockReduceSum(v0 * v0 + v1 * v1);
    float sc = rsqrtf(ss * (1.0f / DMODEL) + 1e-6f);
    size_t base = (size_t)t * DMODEL;
    dst[base + threadIdx.x]       = __float2half(v0 * sc * w[threadIdx.x]);
    dst[base + threadIdx.x + 256] = __float2half(v1 * sc * w[threadIdx.x + 256]);
}

// =================================================================================
// fp32 GEMM 64x64x16 (small xproj/dt), double-buffered, 256 threads, 4x4/thread
// split-K via blockIdx.z. EPI: 0 = store, 1 = softplus(v+bias[col])
// =================================================================================
template <int EPI>
__global__ void __launch_bounds__(256) gemm64_kernel(
    int Kloc,
    const float* __restrict__ A, int lda,
    const float* __restrict__ B, int ldb,
    float* __restrict__ C, int ldc, int partStride,
    const float* __restrict__ bias) {
    __shared__ float As[2][16][68];
    __shared__ float Bs[2][16][68];
    const int tid = threadIdx.x;
    const int bm0 = blockIdx.y * 64, bn0 = blockIdx.x * 64;
    const int kbase = blockIdx.z * Kloc;
    C += (size_t)blockIdx.z * partStride;

    const int lrow = tid >> 2;
    const int kq0  = (tid & 3) << 2;
    const float* Ap = A + (size_t)(bm0 + lrow) * lda + kbase + kq0;
    const float* Bp = B + (size_t)(bn0 + lrow) * ldb + kbase + kq0;

    const int ty = tid >> 4, tx = tid & 15;

    float acc[4][4];
    #pragma unroll
    for (int i = 0; i < 4; i++)
        #pragma unroll
        for (int j = 0; j < 4; j++) acc[i][j] = 0.f;

    float4 av = *reinterpret_cast<const float4*>(Ap);
    float4 bv = *reinterpret_cast<const float4*>(Bp);
    As[0][kq0 + 0][lrow] = av.x; As[0][kq0 + 1][lrow] = av.y;
    As[0][kq0 + 2][lrow] = av.z; As[0][kq0 + 3][lrow] = av.w;
    Bs[0][kq0 + 0][lrow] = bv.x; Bs[0][kq0 + 1][lrow] = bv.y;
    Bs[0][kq0 + 2][lrow] = bv.z; Bs[0][kq0 + 3][lrow] = bv.w;
    __syncthreads();

    const int KT = Kloc >> 4;
    for (int kt = 0; kt < KT; kt++) {
        const int cur = kt & 1, nxt = cur ^ 1;
        if (kt + 1 < KT) {
            int off = (kt + 1) << 4;
            av = *reinterpret_cast<const float4*>(Ap + off);
            bv = *reinterpret_cast<const float4*>(Bp + off);
        }
        #pragma unroll
        for (int kk = 0; kk < 16; kk++) {
            float4 a4 = *reinterpret_cast<const float4*>(&As[cur][kk][ty * 4]);
            float4 b4 = *reinterpret_cast<const float4*>(&Bs[cur][kk][tx * 4]);
            float a[4] = {a4.x, a4.y, a4.z, a4.w};
            float b[4] = {b4.x, b4.y, b4.z, b4.w};
            #pragma unroll
            for (int i = 0; i < 4; i++)
                #pragma unroll
                for (int j = 0; j < 4; j++)
                    acc[i][j] = fmaf(a[i], b[j], acc[i][j]);
        }
        if (kt + 1 < KT) {
            As[nxt][kq0 + 0][lrow] = av.x; As[nxt][kq0 + 1][lrow] = av.y;
            As[nxt][kq0 + 2][lrow] = av.z; As[nxt][kq0 + 3][lrow] = av.w;
            Bs[nxt][kq0 + 0][lrow] = bv.x; Bs[nxt][kq0 + 1][lrow] = bv.y;
            Bs[nxt][kq0 + 2][lrow] = bv.z; Bs[nxt][kq0 + 3][lrow] = bv.w;
            __syncthreads();
        }
    }

    float4 bias4;
    if (EPI == 1) bias4 = *reinterpret_cast<const float4*>(&bias[bn0 + tx * 4]);

    #pragma unroll
    for (int i = 0; i < 4; i++) {
        int row = bm0 + ty * 4 + i;
        float* cp = C + (size_t)row * ldc + bn0 + tx * 4;
        float4 v = make_float4(acc[i][0], acc[i][1], acc[i][2], acc[i][3]);
        if (EPI == 1) {
            v.x += bias4.x; v.y += bias4.y; v.z += bias4.z; v.w += bias4.w;
            v.x = (v.x > 20.f) ? v.x : log1pf(expf(v.x));
            v.y = (v.y > 20.f) ? v.y : log1pf(expf(v.y));
            v.z = (v.z > 20.f) ? v.z : log1pf(expf(v.z));
            v.w = (v.w > 20.f) ? v.w : log1pf(expf(v.w));
        }
        *reinterpret_cast<float4*>(cp) = v;
    }
}

// ---------------- reduce the 4 split-K partials of xproj ----------------
__global__ void reduce4_kernel(float* __restrict__ dst) {
    int i = blockIdx.x * blockDim.x + threadIdx.x;
    if (i >= LSEQ * XDIM) return;
    dst[i] = g_xpart[i] + g_xpart[i + LSEQ * XDIM]
           + g_xpart[i + 2 * LSEQ * XDIM] + g_xpart[i + 3 * LSEQ * XDIM];
}

// ---------------- depthwise causal conv (width 4) + bias + silu ----------------
__global__ void conv_silu_kernel(const float* __restrict__ cw,
                                 const float* __restrict__ cb) {
    int i = blockIdx.x * blockDim.x + threadIdx.x;
    if (i >= LSEQ * DINNER) return;
    int c = i & (DINNER - 1);
    int t = i >> 10;
    float v = cb[c];
    #pragma unroll
    for (int k = 0; k < DCONV; k++) {
        int tt = t - (DCONV - 1) + k;
        if (tt >= 0)
            v = fmaf(g_xz[(size_t)tt * (2 * DINNER) + c], cw[c * DCONV + k], v);
    }
    g_u[i] = v / (1.f + expf(-v));   // silu
}

// ---------------- selective scan (fused y-combine, emits fp16) ----------------
__global__ void scan_kernel(const float* __restrict__ delta,
                            const float* __restrict__ u,
                            const float* __restrict__ xdbl,
                            const float* __restrict__ A_log,
                            const float* __restrict__ xz,
                            const float* __restrict__ Dp,
                            __half* __restrict__ yout) {
    int warp = threadIdx.x >> 5;
    int lane = threadIdx.x & 31;
    int half = lane >> 4;
    int s    = lane & 15;
    int ch   = blockIdx.x * 8 + warp * 2 + half;

    float A2 = -__expf(A_log[ch * DSTATE + s]) * 1.44269504088896f;
    float dpv = Dp[ch];
    float h = 0.f;
    const float* Bp = xdbl + DTRANK;
    const float* Cp = xdbl + DTRANK + DSTATE;

    for (int t0 = 0; t0 < LSEQ; t0 += 16) {
        float dv[16], uv[16], bv[16], cv[16];
        #pragma unroll
        for (int j = 0; j < 16; j++) {
            int t = t0 + j;
            dv[j] = delta[(size_t)t * DINNER + ch];
            uv[j] = u[(size_t)t * DINNER + ch];
            bv[j] = Bp[(size_t)t * XDIM + s];
            cv[j] = Cp[(size_t)t * XDIM + s];
        }
        float p[16];
        #pragma unroll
        for (int j = 0; j < 16; j++) {
            float dA  = exp2f(dv[j] * A2);
            float dbu = dv[j] * uv[j] * bv[j];
            h = fmaf(dA, h, dbu);
            p[j] = h * cv[j];
        }
        float out = 0.f;
        #pragma unroll
        for (int j = 0; j < 16; j++) {
            float v = p[j];
            v += __shfl_xor_sync(0xffffffffu, v, 1);
            v += __shfl_xor_sync(0xffffffffu, v, 2);
            v += __shfl_xor_sync(0xffffffffu, v, 4);
            v += __shfl_xor_sync(0xffffffffu, v, 8);
            if (s == j) out = v;
        }
        int t = t0 + s;
        float uo = u[(size_t)t * DINNER + ch];
        float zz = xz[(size_t)t * (2 * DINNER) + DINNER + ch];
        float sz = zz / (1.f + expf(-zz));
        yout[(size_t)t * DINNER + ch] = __float2half((out + uo * dpv) * sz);
    }
}

// ---------------- cross-entropy loss over logits ----------------
__global__ void loss_init_kernel() { g_loss[0] = 0.f; g_loss[1] = 0.f; }

__global__ void loss_kernel(const int* __restrict__ labels,
                            const float* __restrict__ logits) {
    int t = blockIdx.x;
    const float* row = logits + (size_t)t * VOCAB;
    float mx = -1e30f;
    for (int j = threadIdx.x; j < VOCAB; j += 256) mx = fmaxf(mx, row[j]);
    mx = blockReduceMax(mx);
    float sum = 0.f;
    for (int j = threadIdx.x; j < VOCAB; j += 256) sum += expf(row[j] - mx);
    sum = blockReduceSum(sum);
    if (threadIdx.x == 0) {
        int tgt = labels[t + 1];
        if (tgt != -100) {
            float lp = row[tgt] - mx - logf(sum);
            atomicAdd(&g_loss[0], -lp);
            atomicAdd(&g_loss[1], 1.f);
        }
    }
}

__global__ void loss_final_kernel(float* __restrict__ out, int idx) {
    out[idx] = g_loss[0] / fmaxf(g_loss[1], 1.f);
}

// ---------------- driver ----------------
extern "C" void kernel_launch(void* const* d_in, const int* in_sizes, int n_in,
                              void* d_out, int out_size) {
    const int*   ids    = (const int*)  d_in[0];
    const int*   labels = (const int*)  d_in[1];
    const float* emb    = (const float*)d_in[2];
    const float* pos    = (const float*)d_in[3];
    const float* fnw    = (const float*)d_in[4];
    const float* nw     = (const float*)d_in[5];
    const float* inw    = (const float*)d_in[6];
    const float* cw     = (const float*)d_in[7];
    const float* cb     = (const float*)d_in[8];
    const float* xw     = (const float*)d_in[9];
    const float* dw     = (const float*)d_in[10];
    const float* db     = (const float*)d_in[11];
    const float* alog   = (const float*)d_in[12];
    const float* dp     = (const float*)d_in[13];
    const float* ow     = (const float*)d_in[14];
    float* out = (float*)d_out;

    float *ph, *pxz, *pu, *pxd, *pxpart, *pdelta;
    __half *pa16, *pwe16, *pwi16, *pwo16;
    cudaGetSymbolAddress((void**)&ph,     g_h);
    cudaGetSymbolAddress((void**)&pxz,    g_xz);
    cudaGetSymbolAddress((void**)&pu,     g_u);
    cudaGetSymbolAddress((void**)&pxd,    g_xdbl);
    cudaGetSymbolAddress((void**)&pxpart, g_xpart);
    cudaGetSymbolAddress((void**)&pdelta, g_delta);
    cudaGetSymbolAddress((void**)&pa16,   g_a16);
    cudaGetSymbolAddress((void**)&pwe16,  g_wemb16);
    cudaGetSymbolAddress((void**)&pwi16,  g_win16);
    cudaGetSymbolAddress((void**)&pwo16,  g_wout16);

    cudaFuncSetAttribute(gemm_hmma_kernel<0>,
        cudaFuncAttributeMaxDynamicSharedMemorySize, HT_SMEM_BYTES);
    cudaFuncSetAttribute(gemm_hmma_kernel<2>,
        cudaFuncAttributeMaxDynamicSharedMemorySize, HT_SMEM_BYTES);

    // convert weights to fp16
    cvt_kernel<<<(VOCAB * DMODEL / 4 + 255) / 256, 256>>>(emb, pwe16, VOCAB * DMODEL);
    cvt_kernel<<<(NLAYER * 2 * DINNER * DMODEL / 4 + 255) / 256, 256>>>(
        inw, pwi16, NLAYER * 2 * DINNER * DMODEL);
    cvt_kernel<<<(NLAYER * DMODEL * DINNER / 4 + 255) / 256, 256>>>(
        ow, pwo16, NLAYER * DMODEL * DINNER);

    embed_kernel<<<(LSEQ * DMODEL + 255) / 256, 256>>>(ids, emb, pos);

    for (int l = 0; l < NLAYER; l++) {
        const float* nw_l  = nw   + (size_t)l * DMODEL;
        const float* cw_l  = cw   + (size_t)l * DINNER * DCONV;
        const float* cb_l  = cb   + (size_t)l * DINNER;
        const float* xw_l  = xw   + (size_t)l * XDIM * DINNER;
        const float* dw_l  = dw   + (size_t)l * DINNER * DTRANK;
        const float* db_l  = db   + (size_t)l * DINNER;
        const float* al_l  = alog + (size_t)l * DINNER * DSTATE;
        const float* dp_l  = dp   + (size_t)l * DINNER;
        const __half* wi_l = pwi16 + (size_t)l * 2 * DINNER * DMODEL;
        const __half* wo_l = pwo16 + (size_t)l * DMODEL * DINNER;

        // x = rmsnorm(h) -> fp16
        rmsnorm_kernel<<<LSEQ, 256>>>(ph, nw_l, pa16);
        // xz = x @ in_w^T  [2048 x 2048], K=512 (HMMA fp16)
        gemm_hmma_kernel<0><<<dim3(2 * DINNER / 128, LSEQ / 128), 256, HT_SMEM_BYTES>>>(
            DMODEL, pa16, DMODEL, wi_l, DMODEL, pxz, 2 * DINNER, nullptr);
        // u = silu(causal depthwise conv(xi) + b)
        conv_silu_kernel<<<(LSEQ * DINNER + 255) / 256, 256>>>(cw_l, cb_l);
        // xdbl = u @ xproj_w^T  [2048 x 64], K=1024, split-K x4 (fp32)
        gemm64_kernel<0><<<dim3(1, LSEQ / 64, 4), 256>>>(
            DINNER / 4, pu, DINNER, xw_l, DINNER, pxpart, XDIM, LSEQ * XDIM, nullptr);
        reduce4_kernel<<<(LSEQ * XDIM + 255) / 256, 256>>>(pxd);
        // delta = softplus(dt @ dt_w^T + dt_b)  [2048 x 1024], K=32 (fp32)
        gemm64_kernel<1><<<dim3(DINNER / 64, LSEQ / 64), 256>>>(
            DTRANK, pxd, XDIM, dw_l, DTRANK, pdelta, DINNER, 0, db_l);
        // selective scan + fused (y + u*Dp)*silu(z) -> fp16
        scan_kernel<<<DINNER / 8, 128>>>(pdelta, pu, pxd, al_l, pxz, dp_l, pa16);
        // h = h + yf @ out_w^T  [2048 x 512], K=1024 (HMMA fp16)
        gemm_hmma_kernel<2><<<dim3(DMODEL / 128, LSEQ / 128), 256, HT_SMEM_BYTES>>>(
            DINNER, pa16, DINNER, wo_l, DINNER, ph, DMODEL, ph);
    }

    // final norm + logits (HMMA fp16)
    rmsnorm_kernel<<<LSEQ, 256>>>(ph, fnw, pa16);
    gemm_hmma_kernel<0><<<dim3(VOCAB / 128, LSEQ / 128), 256, HT_SMEM_BYTES>>>(
        DMODEL, pa16, DMODEL, pwe16, DMODEL, out, VOCAB, nullptr);

    // loss
    loss_init_kernel<<<1, 1>>>();
    loss_kernel<<<LSEQ - 1, 256>>>(labels, out);
    loss_final_kernel<<<1, 1>>>(out, out_size - 1);
}